// round 3
// baseline (speedup 1.0000x reference)
#include <cuda_runtime.h>
#include <cstdint>

#define KK    1024
#define LL    4087        // 4*K - 9
#define BB    2048
#define NCH   4096        // 2048 batch * {pred,targ}
#define NPAIR 2048
#define NSTEP 1021        // rows 0..1020; row 0 consumed by prologue
#define SPAD  1024
#define EPSF  1e-6f

#define CTLO ((float)(-1.0 + 1e-6))
#define CTHI ((float)( 1.0 - 1e-6))

// Scratch planes, [row][...]:
//   g_Q4: per chain (A,B,C,l)            [row][chain]   67 MB
//   g_E4: per pair (eA/l1, eA/l0, eB/l1, eB/l0) [row][pair] 33.5 MB
__device__ float4 g_Q4[(size_t)SPAD * NCH];
__device__ float4 g_E4[(size_t)SPAD * NPAIR];
__device__ double g_part[64];

__device__ __forceinline__ float clip1(float x) {
    return fminf(fmaxf(x, -1.0f), 1.0f);
}

// ---------------------------------------------------------------------------
// Kernel 1: parameter precompute + smem transpose to [row][chain] planes.
// ---------------------------------------------------------------------------
__global__ __launch_bounds__(256)
void precompute_kernel(const float* __restrict__ pred,
                       const float* __restrict__ targ)
{
    __shared__ float4 s1[32][33];
    __shared__ float2 s2[32][33];

    const int i0 = blockIdx.x * 32;
    const int c0 = blockIdx.y * 32;
    const int x  = threadIdx.x;

    for (int r = threadIdx.y; r < 32; r += 8) {
        const int c = c0 + r;
        const int i = i0 + x;
        if (i < NSTEP) {
            const int b   = c >> 1;
            const int src = c & 1;
            const float* base = (src ? targ : pred) + (size_t)b * LL;

            float s0  = base[2 * i];
            float s1v = base[2 * i + 1];
            float vb0 = base[3064 + i];   // bl[i]
            float vb1 = base[3065 + i];   // bl[i+1]
            float vb2 = base[3066 + i];   // bl[i+2]
            float vd  = base[2043 + i];   // d13[i+1]
            if (src == 0) {
                s0 = clip1(s0); s1v = clip1(s1v);
                vb0 = clip1(vb0); vb1 = clip1(vb1); vb2 = clip1(vb2);
                vd = clip1(vd);
            }
            const float l0 = fmaf(vb0, 1.05f, 1.95f);
            const float l1 = fmaf(vb1, 1.05f, 1.95f);
            const float l2 = fmaf(vb2, 1.05f, 1.95f);
            const float dd = fmaf(vd, 1.75f, 3.25f);

            float ct = (l1 * l1 + l2 * l2 - dd * dd) / (2.0f * l1 * l2);
            ct = fminf(fmaxf(ct, CTLO), CTHI);
            const float st = sqrtf((1.0f - ct) * (1.0f + ct));

            const float h2 = s0 * s0 + s1v * s1v;
            float cx, sx;
            if (h2 > 0.0f) {
                const float rin = rsqrtf(h2);
                cx = s1v * rin;
                sx = s0 * rin;
            } else {
                cx = 1.0f; sx = 0.0f;
            }

            float4 q1;
            q1.x = -ct;
            q1.y = st * cx;
            q1.z = st * sx;
            q1.w = l2;
            s1[r][x] = q1;
            s2[r][x] = make_float2(EPSF / l1, EPSF / l0);
        }
    }
    __syncthreads();

    for (int r = threadIdx.y; r < 32; r += 8) {
        const int i = i0 + r;
        if (i < NSTEP) {
            const int c = c0 + x;
            g_Q4[(size_t)i * NCH + c] = s1[x][r];
            // pair-packed eps plane: chain A -> .xy, chain B -> .zw
            ((float2*)g_E4)[(size_t)i * NCH + c] = s2[x][r];
        }
    }
}

// ---------------------------------------------------------------------------
// Kernel 2: serial scan, pred+targ of one batch element per thread.
// ---------------------------------------------------------------------------
struct Ch { float Upx, Upy, Upz, Ux, Uy, Uz; };

__device__ __forceinline__ void iter_chain(Ch& S, const float4 q1,
                                           const float e1, const float e0,
                                           float& Nx, float& Ny, float& Nz)
{
    const float CRx = fmaf(S.Upy, S.Uz, -S.Upz * S.Uy);
    const float CRy = fmaf(S.Upz, S.Ux, -S.Upx * S.Uz);
    const float CRz = fmaf(S.Upx, S.Uy, -S.Upy * S.Ux);
    const float MRx = fmaf(CRy, S.Uz, -CRz * S.Uy);
    const float MRy = fmaf(CRz, S.Ux, -CRx * S.Uz);
    const float MRz = fmaf(CRx, S.Uy, -CRy * S.Ux);

    const float uu = fmaf(S.Ux, S.Ux, fmaf(S.Uy, S.Uy, S.Uz * S.Uz));
    const float cc = fmaf(CRx, CRx, fmaf(CRy, CRy, CRz * CRz));

    // hl = 1/(sqrt(uu) + e1), uu ~ 1: polynomial (err < 1e-9)
    const float z  = uu - 1.0f;
    const float d  = fmaf(z, fmaf(-0.125f, z, 0.5f), e1);
    const float hl = fmaf(d, d - 1.0f, 1.0f);

    // cn = 1/(sqrt(cc) + e0): rsqrt + Newton + quadratic eps-correction
    const float rs  = rsqrtf(cc);
    const float a1  = cc * rs;
    const float b1  = a1 * rs;
    const float c1  = fmaf(-0.5f, b1, 1.5f);
    const float rs1 = rs * c1;
    const float xx  = e0 * rs1;
    const float cn  = rs1 * fmaf(xx, xx - 1.0f, 1.0f);
    const float cm  = cn * hl;

    const float al = q1.x * hl;
    const float be = q1.y * cm;
    const float ga = q1.z * cn;

    Nx = fmaf(al, S.Ux, fmaf(be, MRx, ga * CRx));
    Ny = fmaf(al, S.Uy, fmaf(be, MRy, ga * CRy));
    Nz = fmaf(al, S.Uz, fmaf(be, MRz, ga * CRz));

    S.Upx = S.Ux; S.Upy = S.Uy; S.Upz = S.Uz;
    S.Ux = Nx; S.Uy = Ny; S.Uz = Nz;
}

__device__ __forceinline__ void init_chain(const float* __restrict__ base, bool clip,
                                           const float4 r0, Ch& S,
                                           float& bl0o, float& a2x, float& a2y,
                                           float& p0x, float& p0y, float& p0z)
{
    float vb0 = base[3064], vb1 = base[3065], vd = base[2042];
    if (clip) { vb0 = clip1(vb0); vb1 = clip1(vb1); vd = clip1(vd); }
    const float bl0 = fmaf(vb0, 1.05f, 1.95f);
    const float bl1 = fmaf(vb1, 1.05f, 1.95f);
    const float d0  = fmaf(vd, 1.75f, 3.25f);
    float ct = (bl0 * bl0 + bl1 * bl1 - d0 * d0) / (2.0f * bl0 * bl1);
    ct = fminf(fmaxf(ct, CTLO), CTHI);
    const float st = sqrtf((1.0f - ct) * (1.0f + ct));

    const float ex = -bl1 * ct, ey = bl1 * st;
    const float nn = sqrtf(ex * ex + ey * ey);
    const float f  = 1.0f / (nn + EPSF);
    const float bcx = ex * f, bcy = ey * f;
    const float v   = bl0 * bcy;
    const float nz0 = v / (v + EPSF);
    const float m0x = -nz0 * bcy, m0y = nz0 * bcx;

    const float U0x = fmaf(r0.x, bcx, r0.y * m0x);
    const float U0y = fmaf(r0.x, bcy, r0.y * m0y);
    const float U0z = r0.z * nz0;

    bl0o = bl0;
    a2x  = bl0 + ex;
    a2y  = ey;
    p0x  = fmaf(r0.w, U0x, a2x);
    p0y  = fmaf(r0.w, U0y, ey);
    p0z  = r0.w * U0z;

    S.Upx = -ct; S.Upy = st; S.Upz = 0.0f;
    S.Ux = U0x; S.Uy = U0y; S.Uz = U0z;
}

__global__ __launch_bounds__(32)
void scan_kernel(const float* __restrict__ pred,
                 const float* __restrict__ targ)
{
    const int b = blockIdx.x * 32 + threadIdx.x;
    const float* bA = pred + (size_t)b * LL;   // pred (clipped)
    const float* bB = targ + (size_t)b * LL;   // targ

    const float4* q4 = g_Q4 + 2 * (size_t)b;   // chain A at +0, B at +1
    const float4* e4 = g_E4 + b;               // per-pair eps plane

    // ---- prologue: first three atoms + first scan step (row 0) ----
    Ch SA, SB;
    float blA, a2xA, a2yA, pxA, pyA, pzA;
    float blB, a2xB, a2yB, pxB, pyB, pzB;
    init_chain(bA, true,  q4[0], SA, blA, a2xA, a2yA, pxA, pyA, pzA);
    init_chain(bB, false, q4[1], SB, blB, a2xB, a2yB, pxB, pyB, pzB);

    float acc = 0.0f;
    {   // a1 diff (x only)
        const float dx = blA - blB;
        acc = fmaf(dx, dx, acc);
    }
    {   // a2 diff (x,y)
        const float dx = a2xA - a2xB;
        const float dy = a2yA - a2yB;
        acc = fmaf(dx, dx, acc);
        acc = fmaf(dy, dy, acc);
    }
    // position difference state (only diffs matter from here on)
    float dpx = pxA - pxB, dpy = pyA - pyB, dpz = pzA - pzB;
    acc = fmaf(dpx, dpx, acc);
    acc = fmaf(dpy, dpy, acc);
    acc = fmaf(dpz, dpz, acc);

    // ---- main loop: rows 1..1020, groups of 4, double-buffered ----
    float4 QA[4][2], QB[4][2], EA[4], EB[4];

#pragma unroll
    for (int u = 0; u < 4; u++) {
        QA[u][0] = q4[(size_t)(1 + u) * NCH];
        QA[u][1] = q4[(size_t)(1 + u) * NCH + 1];
        EA[u]    = e4[(size_t)(1 + u) * NPAIR];
    }

    auto pair_step = [&](const float4 qA, const float4 qB, const float4 E) {
        float NxA, NyA, NzA, NxB, NyB, NzB;
        iter_chain(SA, qA, E.x, E.y, NxA, NyA, NzA);
        iter_chain(SB, qB, E.z, E.w, NxB, NyB, NzB);
        dpx = fmaf(qA.w, NxA, dpx); dpx = fmaf(-qB.w, NxB, dpx);
        dpy = fmaf(qA.w, NyA, dpy); dpy = fmaf(-qB.w, NyB, dpy);
        dpz = fmaf(qA.w, NzA, dpz); dpz = fmaf(-qB.w, NzB, dpz);
        acc = fmaf(dpx, dpx, acc);
        acc = fmaf(dpy, dpy, acc);
        acc = fmaf(dpz, dpz, acc);
    };

    for (int g = 0; g < 253; g += 2) {
        const size_t rB = 1 + (size_t)(g + 1) * 4;
#pragma unroll
        for (int u = 0; u < 4; u++) {
            QB[u][0] = q4[(rB + u) * NCH];
            QB[u][1] = q4[(rB + u) * NCH + 1];
            EB[u]    = e4[(rB + u) * NPAIR];
        }
#pragma unroll
        for (int u = 0; u < 4; u++) pair_step(QA[u][0], QA[u][1], EA[u]);

        const size_t rA = 1 + (size_t)(g + 2) * 4;
#pragma unroll
        for (int u = 0; u < 4; u++) {
            QA[u][0] = q4[(rA + u) * NCH];
            QA[u][1] = q4[(rA + u) * NCH + 1];
            EA[u]    = e4[(rA + u) * NPAIR];
        }
#pragma unroll
        for (int u = 0; u < 4; u++) pair_step(QB[u][0], QB[u][1], EB[u]);
    }
    // tail: group 254 (rows 1017..1020) sits in A
#pragma unroll
    for (int u = 0; u < 4; u++) pair_step(QA[u][0], QA[u][1], EA[u]);

    // warp reduction -> deterministic per-block partial
#pragma unroll
    for (int off = 16; off; off >>= 1)
        acc += __shfl_xor_sync(0xffffffffu, acc, off);
    if (threadIdx.x == 0)
        g_part[blockIdx.x] = (double)acc;
}

// ---------------------------------------------------------------------------
// Kernel 3: deterministic finalize.
// ---------------------------------------------------------------------------
__global__ void finalize_kernel(float* __restrict__ out)
{
    double s = 0.0;
#pragma unroll 8
    for (int i = 0; i < 64; i++) s += g_part[i];
    out[0] = (float)(s / ((double)BB * (double)KK * 3.0));
}

extern "C" void kernel_launch(void* const* d_in, const int* in_sizes, int n_in,
                              void* d_out, int out_size)
{
    const float* pred = (const float*)d_in[0];
    const float* targ = (const float*)d_in[1];

    dim3 pblk(32, 8, 1);
    dim3 pgrd(32, 128, 1);
    precompute_kernel<<<pgrd, pblk>>>(pred, targ);

    scan_kernel<<<64, 32>>>(pred, targ);

    finalize_kernel<<<1, 1>>>((float*)d_out);
}